// round 16
// baseline (speedup 1.0000x reference)
#include <cuda_runtime.h>
#include <cstdint>

#define BB   4
#define CC   128
#define HW   224
#define PHW  7
#define PP   49
#define ALPHA 0.5f

#define N_OUT 25690112ull
#define N_SCC 67108864ull

// smem: FI [128 rows][32 col-pairs][2 splits] u32, stride 72 u32/row (288B)
//       FtI [56 rows][64 ch-pairs][2 splits] u32, stride 136 u32/row (544B)
//       mu[128] f32
#define FI_U32S   72        // u32 per F row
#define FI_U2S    36        // uint2 per F row
#define FI_U16S   144       // u16 per F row
#define FT_U2S    68        // uint2 per Ft row
#define FT_U16S   272       // u16 per Ft row
#define OFF_FT    36864     // 128*72*4
#define OFF_MU    67328     // OFF_FT + 56*136*4
#define SMEM_BYTES 67840

__device__ __forceinline__ uint16_t f2bf(float x) {
    uint16_t r; asm("cvt.rn.bf16.f32 %0, %1;" : "=h"(r) : "f"(x)); return r;
}
__device__ __forceinline__ float bf2f(uint16_t b) {
    return __uint_as_float(((uint32_t)b) << 16);
}
__device__ __forceinline__ uint32_t packbf(float lo, float hi) {
    uint32_t r; asm("cvt.rn.bf16x2.f32 %0, %1, %2;" : "=r"(r) : "f"(hi), "f"(lo)); return r;
}
__device__ __forceinline__ float lof(uint32_t r) { return __uint_as_float(r << 16); }
__device__ __forceinline__ float hif(uint32_t r) { return __uint_as_float(r & 0xffff0000u); }

__device__ __forceinline__ void mma16(float* c,
                                      uint32_t a0, uint32_t a1, uint32_t a2, uint32_t a3,
                                      uint32_t b0, uint32_t b1) {
    asm volatile("mma.sync.aligned.m16n8k16.row.col.f32.bf16.bf16.f32 "
        "{%0,%1,%2,%3}, {%4,%5,%6,%7}, {%8,%9}, {%0,%1,%2,%3};"
        : "+f"(c[0]), "+f"(c[1]), "+f"(c[2]), "+f"(c[3])
        : "r"(a0), "r"(a1), "r"(a2), "r"(a3), "r"(b0), "r"(b1));
}

__global__ __launch_bounds__(256, 2)
void bdca_mma_kernel(const float* __restrict__ x, const float* __restrict__ beta,
                     float* __restrict__ out, float* __restrict__ Sc,
                     float* __restrict__ cov, float* __restrict__ ecmap)
{
    extern __shared__ char sm[];
    uint16_t*    FIh  = (uint16_t*)sm;
    const uint2* FI2  = (const uint2*)sm;
    uint16_t*    FtIh = (uint16_t*)(sm + OFF_FT);
    const uint2* FtI2 = (const uint2*)(sm + OFF_FT);
    float*       mu   = (float*)(sm + OFF_MU);

    const int tid = threadIdx.x;
    const int w = tid >> 5, l = tid & 31;
    const int g = l >> 2, tg = l & 3;

    const int bm = blockIdx.x;
    const int b  = bm >> 10, m = bm & 1023;
    const int hh = m >> 5, ww = m & 31;
    const size_t xoff = (size_t)b * (CC * HW * HW) + (size_t)(hh * PHW) * HW + (size_t)(ww * PHW);

    // ---- stage: x -> bf16 splits, interleaved (s0,s1) word pairs; pad p>=49 zero ----
    for (int idx = tid; idx < CC * 64; idx += 256) {
        int c = idx >> 6, p = idx & 63;
        float xv = 0.f;
        if (p < PP) {
            int i = p / PHW, j = p - i * PHW;
            xv = __ldg(x + xoff + (size_t)c * (HW * HW) + i * HW + j);
        }
        uint16_t b0 = f2bf(xv);
        uint16_t b1 = f2bf(xv - bf2f(b0));
        int fi = c * FI_U16S + (p >> 1) * 4 + (p & 1);
        FIh[fi]     = b0;
        FIh[fi + 2] = b1;
        if (p < 56) {
            int ti = p * FT_U16S + (c >> 1) * 4 + (c & 1);
            FtIh[ti]     = b0;
            FtIh[ti + 2] = b1;
        }
    }
    __syncthreads();

    // ---- mu: warp w owns channels 16w..16w+15 ----
    {
        #pragma unroll 4
        for (int cc = 0; cc < 16; cc++) {
            int c = 16 * w + cc;
            int f0 = c * FI_U16S + (l >> 1) * 4 + (l & 1);
            float v = bf2f(FIh[f0]) + bf2f(FIh[f0 + 2]);
            if (l < 17) {
                int p2 = 32 + l;
                int f1 = c * FI_U16S + (p2 >> 1) * 4 + (p2 & 1);
                v += bf2f(FIh[f1]) + bf2f(FIh[f1 + 2]);
            }
            #pragma unroll
            for (int o = 16; o; o >>= 1) v += __shfl_xor_sync(0xffffffffu, v, o);
            if (l == 0) mu[c] = v * (1.f / 49.f);
        }
    }
    __syncthreads();

    const int r1 = 16 * w + g;

    // ---- GEMM1: G = F * F^T, 4 K16 tiles, 3-product bf16 split, LDS.64 fragments ----
    float acc[16][4];
    #pragma unroll
    for (int n = 0; n < 16; n++)
        #pragma unroll
        for (int j = 0; j < 4; j++) acc[n][j] = 0.f;

    #pragma unroll 1
    for (int kt = 0; kt < 4; kt++) {
        const int ka = 8 * kt + tg;
        uint2 A0 = FI2[r1 * FI_U2S + ka];
        uint2 A1 = FI2[(r1 + 8) * FI_U2S + ka];
        uint2 A2 = FI2[r1 * FI_U2S + ka + 4];
        uint2 A3 = FI2[(r1 + 8) * FI_U2S + ka + 4];
        #pragma unroll
        for (int n = 0; n < 16; n++) {
            const int bb = (8 * n + g) * FI_U2S + ka;
            uint2 B0 = FI2[bb];
            uint2 B1 = FI2[bb + 4];
            mma16(acc[n], A0.x, A1.x, A2.x, A3.x, B0.x, B1.x);
            mma16(acc[n], A0.x, A1.x, A2.x, A3.x, B0.y, B1.y);
            mma16(acc[n], A0.y, A1.y, A2.y, A3.y, B0.x, B1.x);
        }
    }

    // ---- softmax row stats (rows r1, r1+8) ----
    float mx1 = -3.4e38f, mx2 = -3.4e38f;
    #pragma unroll
    for (int n = 0; n < 16; n++) {
        mx1 = fmaxf(mx1, fmaxf(acc[n][0], acc[n][1]));
        mx2 = fmaxf(mx2, fmaxf(acc[n][2], acc[n][3]));
    }
    mx1 = fmaxf(mx1, __shfl_xor_sync(0xffffffffu, mx1, 1));
    mx1 = fmaxf(mx1, __shfl_xor_sync(0xffffffffu, mx1, 2));
    mx2 = fmaxf(mx2, __shfl_xor_sync(0xffffffffu, mx2, 1));
    mx2 = fmaxf(mx2, __shfl_xor_sync(0xffffffffu, mx2, 2));

    float s1 = 0.f, s2 = 0.f;
    #pragma unroll
    for (int n = 0; n < 16; n++) {
        s1 += __expf(acc[n][0] - mx1) + __expf(acc[n][1] - mx1);
        s2 += __expf(acc[n][2] - mx2) + __expf(acc[n][3] - mx2);
    }
    s1 += __shfl_xor_sync(0xffffffffu, s1, 1);
    s1 += __shfl_xor_sync(0xffffffffu, s1, 2);
    s2 += __shfl_xor_sync(0xffffffffu, s2, 1);
    s2 += __shfl_xor_sync(0xffffffffu, s2, 2);
    const float i1 = 1.f / s1, i2 = 1.f / s2;
    const float m1 = mu[r1], m2 = mu[r1 + 8];

    // ---- epilogue A: Sc/cov to gmem; L replaces G in acc (C-fragment layout) ----
    {
        const size_t ob = (size_t)bm << 14;
        #pragma unroll
        for (int n = 0; n < 16; n++) {
            int col = 8 * n + 2 * tg;
            float2 mc = *(float2*)(mu + col);
            float sc0 = __expf(acc[n][0] - mx1) * i1;
            float sc1 = __expf(acc[n][1] - mx1) * i1;
            float sc2 = __expf(acc[n][2] - mx2) * i2;
            float sc3 = __expf(acc[n][3] - mx2) * i2;
            float cv0 = acc[n][0] * (1.f / 49.f) - m1 * mc.x;
            float cv1 = acc[n][1] * (1.f / 49.f) - m1 * mc.y;
            float cv2 = acc[n][2] * (1.f / 49.f) - m2 * mc.x;
            float cv3 = acc[n][3] * (1.f / 49.f) - m2 * mc.y;
            *(float2*)(Sc  + ob + (size_t)r1 * 128 + col)       = make_float2(sc0, sc1);
            *(float2*)(Sc  + ob + (size_t)(r1 + 8) * 128 + col) = make_float2(sc2, sc3);
            *(float2*)(cov + ob + (size_t)r1 * 128 + col)       = make_float2(cv0, cv1);
            *(float2*)(cov + ob + (size_t)(r1 + 8) * 128 + col) = make_float2(cv2, cv3);
            acc[n][0] = fmaf(ALPHA, cv0, sc0);
            acc[n][1] = fmaf(ALPHA, cv1, sc1);
            acc[n][2] = fmaf(ALPHA, cv2, sc2);
            acc[n][3] = fmaf(ALPHA, cv3, sc3);
        }
    }

    // ---- GEMM2: Ec = L * F, 8 K16 tiles. A direct from acc; B via LDS.64 ----
    float acc2[7][4];
    #pragma unroll
    for (int n = 0; n < 7; n++)
        #pragma unroll
        for (int j = 0; j < 4; j++) acc2[n][j] = 0.f;

    #pragma unroll
    for (int kk = 0; kk < 8; kk++) {
        uint32_t a0 = packbf(acc[2*kk][0],     acc[2*kk][1]);
        uint32_t a1 = packbf(acc[2*kk][2],     acc[2*kk][3]);
        uint32_t a2 = packbf(acc[2*kk + 1][0], acc[2*kk + 1][1]);
        uint32_t a3 = packbf(acc[2*kk + 1][2], acc[2*kk + 1][3]);
        uint32_t r0 = packbf(acc[2*kk][0] - lof(a0),     acc[2*kk][1] - hif(a0));
        uint32_t r1f = packbf(acc[2*kk][2] - lof(a1),    acc[2*kk][3] - hif(a1));
        uint32_t r2 = packbf(acc[2*kk + 1][0] - lof(a2), acc[2*kk + 1][1] - hif(a2));
        uint32_t r3 = packbf(acc[2*kk + 1][2] - lof(a3), acc[2*kk + 1][3] - hif(a3));
        const int kb = 8 * kk + tg;
        #pragma unroll
        for (int n = 0; n < 7; n++) {
            const int bb = (8 * n + g) * FT_U2S + kb;
            uint2 B0 = FtI2[bb];
            uint2 B1 = FtI2[bb + 4];
            mma16(acc2[n], a0, a1, a2, a3, B0.x, B1.x);
            mma16(acc2[n], a0, a1, a2, a3, B0.y, B1.y);
            mma16(acc2[n], r0, r1f, r2, r3, B0.x, B1.x);
        }
    }

    // ---- epilogue B: fold Ec, out = x * (beta*Ec + x) ----
    {
        const float beta0 = beta[0];
        #pragma unroll
        for (int n = 0; n < 7; n++) {
            const int p0 = 8 * n + 2 * tg;
            #pragma unroll
            for (int e = 0; e < 4; e++) {
                int p = p0 + (e & 1);
                int c = (e < 2) ? r1 : (r1 + 8);
                if (p < PP) {
                    int fi = c * FI_U16S + (p >> 1) * 4 + (p & 1);
                    float xv = bf2f(FIh[fi]) + bf2f(FIh[fi + 2]);
                    float ec = acc2[n][e];
                    int i = p / PHW, j = p - i * PHW;
                    size_t ga = xoff + (size_t)c * (HW * HW) + i * HW + j;
                    ecmap[ga] = ec;
                    out[ga]   = xv * fmaf(beta0, ec, xv);
                }
            }
        }
    }
}

extern "C" void kernel_launch(void* const* d_in, const int* in_sizes, int n_in,
                              void* d_out, int out_size)
{
    const float* x    = (const float*)d_in[0];
    const float* beta = (const float*)d_in[1];

    float* out   = (float*)d_out;
    float* Sc    = out + N_OUT;
    float* cov   = Sc + N_SCC;
    float* ecmap = cov + N_SCC;

    cudaFuncSetAttribute(bdca_mma_kernel, cudaFuncAttributeMaxDynamicSharedMemorySize, SMEM_BYTES);
    bdca_mma_kernel<<<BB * 1024, 256, SMEM_BYTES>>>(x, beta, out, Sc, cov, ecmap);
}

// round 17
// speedup vs baseline: 1.1383x; 1.1383x over previous
#include <cuda_runtime.h>
#include <cstdint>

#define BB   4
#define CC   128
#define HW   224
#define PHW  7
#define PP   49
#define ALPHA 0.5f

#define N_OUT 25690112ull
#define N_SCC 67108864ull

// smem (bytes): Fb0[128][72]bf16, Fb1 same, Ft0[56][136]bf16, Ft1 same, mu[128]f32
#define FSB   72          // F bf16 row stride (144B, ==16 mod 128 -> LDSM conflict-free)
#define STB   136         // Ft bf16 row stride (272B, ==16 mod 128)
#define OFF_FB1  18432
#define OFF_FT0  36864
#define OFF_FT1  52096
#define OFF_MU   67328
#define SMEM_BYTES 67840

__device__ __forceinline__ uint32_t smem_u32(const void* p) {
    uint32_t a;
    asm("{ .reg .u64 t; cvta.to.shared.u64 t, %1; cvt.u32.u64 %0, t; }" : "=r"(a) : "l"(p));
    return a;
}
__device__ __forceinline__ uint16_t f2bf(float x) {
    uint16_t r; asm("cvt.rn.bf16.f32 %0, %1;" : "=h"(r) : "f"(x)); return r;
}
__device__ __forceinline__ float bf2f(uint16_t b) {
    return __uint_as_float(((uint32_t)b) << 16);
}
__device__ __forceinline__ uint32_t packbf(float lo, float hi) {
    uint32_t r; asm("cvt.rn.bf16x2.f32 %0, %1, %2;" : "=r"(r) : "f"(hi), "f"(lo)); return r;
}
__device__ __forceinline__ float lof(uint32_t r) { return __uint_as_float(r << 16); }
__device__ __forceinline__ float hif(uint32_t r) { return __uint_as_float(r & 0xffff0000u); }

__device__ __forceinline__ void mma16(float* c,
                                      uint32_t a0, uint32_t a1, uint32_t a2, uint32_t a3,
                                      uint32_t b0, uint32_t b1) {
    asm volatile("mma.sync.aligned.m16n8k16.row.col.f32.bf16.bf16.f32 "
        "{%0,%1,%2,%3}, {%4,%5,%6,%7}, {%8,%9}, {%0,%1,%2,%3};"
        : "+f"(c[0]), "+f"(c[1]), "+f"(c[2]), "+f"(c[3])
        : "r"(a0), "r"(a1), "r"(a2), "r"(a3), "r"(b0), "r"(b1));
}
__device__ __forceinline__ void ldsm4(uint32_t* r, uint32_t a) {
    asm volatile("ldmatrix.sync.aligned.m8n8.x4.shared.b16 {%0,%1,%2,%3}, [%4];"
        : "=r"(r[0]), "=r"(r[1]), "=r"(r[2]), "=r"(r[3]) : "r"(a));
}
__device__ __forceinline__ void ldsm2(uint32_t* r, uint32_t a) {
    asm volatile("ldmatrix.sync.aligned.m8n8.x2.shared.b16 {%0,%1}, [%2];"
        : "=r"(r[0]), "=r"(r[1]) : "r"(a));
}

__global__ __launch_bounds__(256, 2)
void bdca_mma_kernel(const float* __restrict__ x, const float* __restrict__ beta,
                     float* __restrict__ out, float* __restrict__ Sc,
                     float* __restrict__ cov, float* __restrict__ ecmap)
{
    extern __shared__ char sm[];
    uint16_t* Fb0 = (uint16_t*)sm;
    uint16_t* Fb1 = (uint16_t*)(sm + OFF_FB1);
    uint16_t* Ft0 = (uint16_t*)(sm + OFF_FT0);
    uint16_t* Ft1 = (uint16_t*)(sm + OFF_FT1);
    float*    mu  = (float*)(sm + OFF_MU);

    const int tid = threadIdx.x;
    const int w = tid >> 5, l = tid & 31;
    const int g = l >> 2, tg = l & 3;

    const int bm = blockIdx.x;
    const int b  = bm >> 10, m = bm & 1023;
    const int hh = m >> 5, ww = m & 31;
    const size_t xoff = (size_t)b * (CC * HW * HW) + (size_t)(hh * PHW) * HW + (size_t)(ww * PHW);

    // ---- stage: x -> bf16 (b0,b1) into F [c][p] (pad p 49..63 = 0) and Ft [p][c] ----
    for (int idx = tid; idx < CC * 64; idx += 256) {
        int c = idx >> 6, p = idx & 63;
        float xv = 0.f;
        if (p < PP) {
            int i = p / PHW, j = p - i * PHW;
            xv = __ldg(x + xoff + (size_t)c * (HW * HW) + i * HW + j);
        }
        uint16_t b0 = f2bf(xv);
        uint16_t b1 = f2bf(xv - bf2f(b0));
        Fb0[c * FSB + p] = b0;
        Fb1[c * FSB + p] = b1;
        if (p < 56) {
            Ft0[p * STB + c] = b0;
            Ft1[p * STB + c] = b1;
        }
    }
    __syncthreads();

    // ---- mu: warp w owns channels 16w..16w+15 ----
    {
        #pragma unroll 4
        for (int cc = 0; cc < 16; cc++) {
            int c = 16 * w + cc;
            float v = bf2f(Fb0[c * FSB + l]) + bf2f(Fb1[c * FSB + l]);
            if (l < 17) v += bf2f(Fb0[c * FSB + 32 + l]) + bf2f(Fb1[c * FSB + 32 + l]);
            #pragma unroll
            for (int o = 16; o; o >>= 1) v += __shfl_xor_sync(0xffffffffu, v, o);
            if (l == 0) mu[c] = v * (1.f / 49.f);
        }
    }
    __syncthreads();

    const int r1 = 16 * w + g;

    // ---- ldmatrix per-thread base addresses ----
    const uint32_t smb = smem_u32(sm);
    const int lrow8 = l & 7;
    // A (GEMM1): m0 rows0-7/k0-7, m1 rows8-15/k0-7, m2 rows0-7/k8-15, m3 rows8-15/k8-15
    const uint32_t rowA = 16 * w + lrow8 + ((l >> 3) & 1) * 8;
    const uint32_t colA = (l >> 4) * 8;
    const uint32_t aA0 = smb + rowA * 144 + colA * 2;
    const uint32_t aA1 = aA0 + OFF_FB1;
    // B (both GEMMs): m0 rowsN/k0-7, m1 rowsN/k8-15, m2 rowsN+8/k0-7, m3 rowsN+8/k8-15
    const uint32_t rowB = lrow8 + ((l >> 4) << 3);
    const uint32_t colB = ((l >> 3) & 1) * 8;
    const uint32_t aB0 = smb + rowB * 144 + colB * 2;
    const uint32_t aB1 = aB0 + OFF_FB1;
    const uint32_t aT0 = smb + OFF_FT0 + rowB * 272 + colB * 2;

    // ---- GEMM1: G = F * F^T, 4 K16 tiles, 3-product bf16 split, LDSM fragments ----
    float acc[16][4];
    #pragma unroll
    for (int n = 0; n < 16; n++)
        #pragma unroll
        for (int j = 0; j < 4; j++) acc[n][j] = 0.f;

    #pragma unroll 1
    for (int kt = 0; kt < 4; kt++) {
        uint32_t A0[4], A1[4];
        ldsm4(A0, aA0 + kt * 32);
        ldsm4(A1, aA1 + kt * 32);
        #pragma unroll
        for (int np = 0; np < 8; np++) {
            uint32_t B0[4], B1[4];
            ldsm4(B0, aB0 + np * 2304 + kt * 32);
            ldsm4(B1, aB1 + np * 2304 + kt * 32);
            mma16(acc[2*np],   A0[0], A0[1], A0[2], A0[3], B0[0], B0[1]);
            mma16(acc[2*np],   A0[0], A0[1], A0[2], A0[3], B1[0], B1[1]);
            mma16(acc[2*np],   A1[0], A1[1], A1[2], A1[3], B0[0], B0[1]);
            mma16(acc[2*np+1], A0[0], A0[1], A0[2], A0[3], B0[2], B0[3]);
            mma16(acc[2*np+1], A0[0], A0[1], A0[2], A0[3], B1[2], B1[3]);
            mma16(acc[2*np+1], A1[0], A1[1], A1[2], A1[3], B0[2], B0[3]);
        }
    }

    // ---- softmax row stats (rows r1, r1+8) ----
    float mx1 = -3.4e38f, mx2 = -3.4e38f;
    #pragma unroll
    for (int n = 0; n < 16; n++) {
        mx1 = fmaxf(mx1, fmaxf(acc[n][0], acc[n][1]));
        mx2 = fmaxf(mx2, fmaxf(acc[n][2], acc[n][3]));
    }
    mx1 = fmaxf(mx1, __shfl_xor_sync(0xffffffffu, mx1, 1));
    mx1 = fmaxf(mx1, __shfl_xor_sync(0xffffffffu, mx1, 2));
    mx2 = fmaxf(mx2, __shfl_xor_sync(0xffffffffu, mx2, 1));
    mx2 = fmaxf(mx2, __shfl_xor_sync(0xffffffffu, mx2, 2));

    float s1 = 0.f, s2 = 0.f;
    #pragma unroll
    for (int n = 0; n < 16; n++) {
        s1 += __expf(acc[n][0] - mx1) + __expf(acc[n][1] - mx1);
        s2 += __expf(acc[n][2] - mx2) + __expf(acc[n][3] - mx2);
    }
    s1 += __shfl_xor_sync(0xffffffffu, s1, 1);
    s1 += __shfl_xor_sync(0xffffffffu, s1, 2);
    s2 += __shfl_xor_sync(0xffffffffu, s2, 1);
    s2 += __shfl_xor_sync(0xffffffffu, s2, 2);
    const float i1 = 1.f / s1, i2 = 1.f / s2;
    const float m1 = mu[r1], m2 = mu[r1 + 8];

    // ---- epilogue A: Sc/cov to gmem; L replaces G in acc (C-fragment layout) ----
    {
        const size_t ob = (size_t)bm << 14;
        #pragma unroll
        for (int n = 0; n < 16; n++) {
            int col = 8 * n + 2 * tg;
            float2 mc = *(float2*)(mu + col);
            float sc0 = __expf(acc[n][0] - mx1) * i1;
            float sc1 = __expf(acc[n][1] - mx1) * i1;
            float sc2 = __expf(acc[n][2] - mx2) * i2;
            float sc3 = __expf(acc[n][3] - mx2) * i2;
            float cv0 = acc[n][0] * (1.f / 49.f) - m1 * mc.x;
            float cv1 = acc[n][1] * (1.f / 49.f) - m1 * mc.y;
            float cv2 = acc[n][2] * (1.f / 49.f) - m2 * mc.x;
            float cv3 = acc[n][3] * (1.f / 49.f) - m2 * mc.y;
            *(float2*)(Sc  + ob + (size_t)r1 * 128 + col)       = make_float2(sc0, sc1);
            *(float2*)(Sc  + ob + (size_t)(r1 + 8) * 128 + col) = make_float2(sc2, sc3);
            *(float2*)(cov + ob + (size_t)r1 * 128 + col)       = make_float2(cv0, cv1);
            *(float2*)(cov + ob + (size_t)(r1 + 8) * 128 + col) = make_float2(cv2, cv3);
            acc[n][0] = fmaf(ALPHA, cv0, sc0);
            acc[n][1] = fmaf(ALPHA, cv1, sc1);
            acc[n][2] = fmaf(ALPHA, cv2, sc2);
            acc[n][3] = fmaf(ALPHA, cv3, sc3);
        }
    }

    // ---- GEMM2: Ec = L * F, 8 K16 tiles. A direct from acc; B via LDSM on Ft ----
    float acc2[7][4];
    #pragma unroll
    for (int n = 0; n < 7; n++)
        #pragma unroll
        for (int j = 0; j < 4; j++) acc2[n][j] = 0.f;

    #pragma unroll
    for (int kk = 0; kk < 8; kk++) {
        uint32_t a0 = packbf(acc[2*kk][0],     acc[2*kk][1]);
        uint32_t a1 = packbf(acc[2*kk][2],     acc[2*kk][3]);
        uint32_t a2 = packbf(acc[2*kk + 1][0], acc[2*kk + 1][1]);
        uint32_t a3 = packbf(acc[2*kk + 1][2], acc[2*kk + 1][3]);
        uint32_t r0 = packbf(acc[2*kk][0] - lof(a0),     acc[2*kk][1] - hif(a0));
        uint32_t r1f = packbf(acc[2*kk][2] - lof(a1),    acc[2*kk][3] - hif(a1));
        uint32_t r2 = packbf(acc[2*kk + 1][0] - lof(a2), acc[2*kk + 1][1] - hif(a2));
        uint32_t r3 = packbf(acc[2*kk + 1][2] - lof(a3), acc[2*kk + 1][3] - hif(a3));

        uint32_t B0[14], B1[14];   // [tile][khalf] flattened: tile n -> B[2n], B[2n+1]
        #pragma unroll
        for (int np = 0; np < 3; np++) {
            ldsm4(B0 + 4 * np, aT0 + np * 4352 + kk * 32);
            ldsm4(B1 + 4 * np, aT0 + 15232 + np * 4352 + kk * 32);
        }
        ldsm2(B0 + 12, aT0 + 13056 + kk * 32);
        ldsm2(B1 + 12, aT0 + 15232 + 13056 + kk * 32);

        #pragma unroll
        for (int n = 0; n < 7; n++) {
            mma16(acc2[n], a0, a1, a2, a3, B0[2*n], B0[2*n+1]);
            mma16(acc2[n], a0, a1, a2, a3, B1[2*n], B1[2*n+1]);
            mma16(acc2[n], r0, r1f, r2, r3, B0[2*n], B0[2*n+1]);
        }
    }

    // ---- epilogue B: fold Ec, out = x * (beta*Ec + x) ----
    {
        const float beta0 = beta[0];
        #pragma unroll
        for (int n = 0; n < 7; n++) {
            const int p0 = 8 * n + 2 * tg;
            #pragma unroll
            for (int e = 0; e < 4; e++) {
                int p = p0 + (e & 1);
                int c = (e < 2) ? r1 : (r1 + 8);
                if (p < PP) {
                    float xv = bf2f(Fb0[c * FSB + p]) + bf2f(Fb1[c * FSB + p]);
                    float ec = acc2[n][e];
                    int i = p / PHW, j = p - i * PHW;
                    size_t ga = xoff + (size_t)c * (HW * HW) + i * HW + j;
                    ecmap[ga] = ec;
                    out[ga]   = xv * fmaf(beta0, ec, xv);
                }
            }
        }
    }
}

extern "C" void kernel_launch(void* const* d_in, const int* in_sizes, int n_in,
                              void* d_out, int out_size)
{
    const float* x    = (const float*)d_in[0];
    const float* beta = (const float*)d_in[1];

    float* out   = (float*)d_out;
    float* Sc    = out + N_OUT;
    float* cov   = Sc + N_SCC;
    float* ecmap = cov + N_SCC;

    cudaFuncSetAttribute(bdca_mma_kernel, cudaFuncAttributeMaxDynamicSharedMemorySize, SMEM_BYTES);
    bdca_mma_kernel<<<BB * 1024, 256, SMEM_BYTES>>>(x, beta, out, Sc, cov, ecmap);
}